// round 4
// baseline (speedup 1.0000x reference)
#include <cuda_runtime.h>
#include <cstdint>

// ---------------------------------------------------------------------------
// Problem: B=8, T=4096, D=1024.
//   h   = tanh(x @ W1^T + b1)            [B,T,D]
//   s   = h @ w2^T + b2                  [B,T]
//   e   = exp(s - max_b(s)); den = cumsum(e)
//   ctx = cumsum(e * x)/den
//   out = tanh([ctx, x] @ Wc^T + bc)
//
// Restructure: y = x@WcL^T, z = x@WcR^T  (WcL = Wc[:, :D], WcR = Wc[:, D:])
//   ctx@WcL^T = cumsum(e*y)/den   (linearity)
//   out = tanh(cumsum(e*y)/den + z + bc)
// So: one logical GEMM P = x @ [W1; WcL; WcR]^T  (M=32768, N=3072, K=1024),
// then cheap score/scan/epilogue kernels.
// ---------------------------------------------------------------------------

#define B_DIM 8
#define T_DIM 4096
#define D_DIM 1024
#define M_TOK (B_DIM * T_DIM)      // 32768
#define N_P   (3 * D_DIM)          // 3072
#define NCHUNK 32
#define CSIZE (T_DIM / NCHUNK)     // 128

// Scratch (static device globals: allocation-free per harness rules)
__device__ float g_P[(size_t)M_TOK * N_P];            // ~402 MB
__device__ float g_s[M_TOK];
__device__ float g_e[M_TOK];
__device__ float g_invden[M_TOK];
__device__ float g_part[B_DIM * NCHUNK * D_DIM];

// ---------------------------------------------------------------------------
// SGEMM (NT): C[m,n] = sum_k A[m,k] * B[n,k] (+ bias[n])
// A row-major MxK (lda=K), B row-major rows of length >= K (row stride ldb).
// 128x128 tile, BK=16, 256 threads, 8x8 per thread, double-buffered smem.
// ---------------------------------------------------------------------------
__global__ void __launch_bounds__(256, 2) sgemm_nt(
    const float* __restrict__ A, int lda,
    const float* __restrict__ Bm, int ldb,
    const float* __restrict__ bias,     // may be nullptr (indexed by local n)
    float* __restrict__ C, int ldc,     // C already offset to this GEMM's cols
    int K)
{
    constexpr int BM = 128, BN = 128, BK = 16;
    __shared__ float As[2][BK][BM + 4];
    __shared__ float Bs[2][BK][BN + 4];

    const int tid = threadIdx.x;
    const int bm = blockIdx.y, bn = blockIdx.x;
    const float* Ab = A + (size_t)bm * BM * lda;
    const float* Bb = Bm + (size_t)bn * BN * ldb;

    // loader mapping: 512 float4 per tile (128 rows x 4 float4), 2 per thread
    const int row0 = tid >> 2;           // 0..63
    const int row1 = row0 + 64;          // 64..127
    const int c4   = tid & 3;            // float4 column within BK=16
    const int k4   = c4 * 4;

    const int ty = tid >> 4, tx = tid & 15;

    float4 a0, a1, b0, b1;

    // prologue: fetch tile 0
    a0 = *(const float4*)(Ab + (size_t)row0 * lda + k4);
    a1 = *(const float4*)(Ab + (size_t)row1 * lda + k4);
    b0 = *(const float4*)(Bb + (size_t)row0 * ldb + k4);
    b1 = *(const float4*)(Bb + (size_t)row1 * ldb + k4);
    As[0][k4+0][row0]=a0.x; As[0][k4+1][row0]=a0.y; As[0][k4+2][row0]=a0.z; As[0][k4+3][row0]=a0.w;
    As[0][k4+0][row1]=a1.x; As[0][k4+1][row1]=a1.y; As[0][k4+2][row1]=a1.z; As[0][k4+3][row1]=a1.w;
    Bs[0][k4+0][row0]=b0.x; Bs[0][k4+1][row0]=b0.y; Bs[0][k4+2][row0]=b0.z; Bs[0][k4+3][row0]=b0.w;
    Bs[0][k4+0][row1]=b1.x; Bs[0][k4+1][row1]=b1.y; Bs[0][k4+2][row1]=b1.z; Bs[0][k4+3][row1]=b1.w;
    __syncthreads();

    float acc[8][8];
    #pragma unroll
    for (int i = 0; i < 8; i++)
        #pragma unroll
        for (int j = 0; j < 8; j++) acc[i][j] = 0.f;

    int buf = 0;
    for (int kt = 0; kt < K; kt += BK) {
        const int nxt = kt + BK;
        const bool has = (nxt < K);
        if (has) {
            a0 = *(const float4*)(Ab + (size_t)row0 * lda + nxt + k4);
            a1 = *(const float4*)(Ab + (size_t)row1 * lda + nxt + k4);
            b0 = *(const float4*)(Bb + (size_t)row0 * ldb + nxt + k4);
            b1 = *(const float4*)(Bb + (size_t)row1 * ldb + nxt + k4);
        }
        #pragma unroll
        for (int kk = 0; kk < BK; kk++) {
            float af[8], bf[8];
            #pragma unroll
            for (int i = 0; i < 8; i++) af[i] = As[buf][kk][ty * 8 + i];
            #pragma unroll
            for (int j = 0; j < 8; j++) bf[j] = Bs[buf][kk][tx * 8 + j];
            #pragma unroll
            for (int i = 0; i < 8; i++)
                #pragma unroll
                for (int j = 0; j < 8; j++)
                    acc[i][j] = fmaf(af[i], bf[j], acc[i][j]);
        }
        if (has) {
            const int nb = buf ^ 1;
            As[nb][k4+0][row0]=a0.x; As[nb][k4+1][row0]=a0.y; As[nb][k4+2][row0]=a0.z; As[nb][k4+3][row0]=a0.w;
            As[nb][k4+0][row1]=a1.x; As[nb][k4+1][row1]=a1.y; As[nb][k4+2][row1]=a1.z; As[nb][k4+3][row1]=a1.w;
            Bs[nb][k4+0][row0]=b0.x; Bs[nb][k4+1][row0]=b0.y; Bs[nb][k4+2][row0]=b0.z; Bs[nb][k4+3][row0]=b0.w;
            Bs[nb][k4+0][row1]=b1.x; Bs[nb][k4+1][row1]=b1.y; Bs[nb][k4+2][row1]=b1.z; Bs[nb][k4+3][row1]=b1.w;
        }
        __syncthreads();
        buf ^= 1;
    }

    // epilogue
    const int c0 = bn * BN + tx * 8;     // column local to this GEMM's N range
    float bl[8];
    #pragma unroll
    for (int j = 0; j < 8; j++) bl[j] = bias ? bias[c0 + j] : 0.f;
    #pragma unroll
    for (int i = 0; i < 8; i++) {
        float* crow = C + (size_t)(bm * BM + ty * 8 + i) * ldc + c0;
        float4 v0 = make_float4(acc[i][0]+bl[0], acc[i][1]+bl[1], acc[i][2]+bl[2], acc[i][3]+bl[3]);
        float4 v1 = make_float4(acc[i][4]+bl[4], acc[i][5]+bl[5], acc[i][6]+bl[6], acc[i][7]+bl[7]);
        *(float4*)(crow)     = v0;
        *(float4*)(crow + 4) = v1;
    }
}

// ---------------------------------------------------------------------------
// s[m] = b2 + sum_e tanh(P1[m,e]) * w2[e]     (P1 = first D columns of P)
// ---------------------------------------------------------------------------
__global__ void __launch_bounds__(256) score_kernel(
    const float* __restrict__ w2, const float* __restrict__ b2)
{
    const int m = blockIdx.x;
    const float* row = g_P + (size_t)m * N_P;
    float acc = 0.f;
    for (int e = threadIdx.x; e < D_DIM; e += 256)
        acc += tanhf(row[e]) * w2[e];
    #pragma unroll
    for (int o = 16; o > 0; o >>= 1) acc += __shfl_down_sync(0xffffffffu, acc, o);
    __shared__ float red[8];
    if ((threadIdx.x & 31) == 0) red[threadIdx.x >> 5] = acc;
    __syncthreads();
    if (threadIdx.x < 8) {
        acc = red[threadIdx.x];
        #pragma unroll
        for (int o = 4; o > 0; o >>= 1) acc += __shfl_down_sync(0xffu, acc, o);
        if (threadIdx.x == 0) g_s[m] = acc + b2[0];
    }
}

// ---------------------------------------------------------------------------
// Per batch: m = max(s); e = exp(s-m); den = inclusive cumsum(e); invden = 1/den
// One block of 1024 threads per batch, each thread owns 4 consecutive t's.
// ---------------------------------------------------------------------------
__global__ void __launch_bounds__(1024) softmax_scan_kernel()
{
    const int b = blockIdx.x, tid = threadIdx.x;
    const int lane = tid & 31, wid = tid >> 5;
    const float4 v = ((const float4*)(g_s + b * T_DIM))[tid];

    float wm = fmaxf(fmaxf(v.x, v.y), fmaxf(v.z, v.w));
    #pragma unroll
    for (int o = 16; o > 0; o >>= 1) wm = fmaxf(wm, __shfl_xor_sync(0xffffffffu, wm, o));
    __shared__ float sred[32];
    if (lane == 0) sred[wid] = wm;
    __syncthreads();
    float bm = sred[0];
    #pragma unroll
    for (int i = 1; i < 32; i++) bm = fmaxf(bm, sred[i]);

    const float e0 = expf(v.x - bm), e1 = expf(v.y - bm),
                e2 = expf(v.z - bm), e3 = expf(v.w - bm);
    const float tsum = e0 + e1 + e2 + e3;

    // inclusive scan of tsum across 1024 threads
    float xs = tsum;
    #pragma unroll
    for (int o = 1; o < 32; o <<= 1) {
        float y = __shfl_up_sync(0xffffffffu, xs, o);
        if (lane >= o) xs += y;
    }
    __shared__ float wsum[32];
    if (lane == 31) wsum[wid] = xs;
    __syncthreads();
    if (wid == 0) {
        float y = wsum[lane];
        #pragma unroll
        for (int o = 1; o < 32; o <<= 1) {
            float z = __shfl_up_sync(0xffffffffu, y, o);
            if (lane >= o) y += z;
        }
        wsum[lane] = y;
    }
    __syncthreads();

    float run = (wid > 0 ? wsum[wid - 1] : 0.f) + (xs - tsum);  // exclusive prefix
    float4 eo, io;
    run += e0; eo.x = e0; io.x = 1.f / run;
    run += e1; eo.y = e1; io.y = 1.f / run;
    run += e2; eo.z = e2; io.z = 1.f / run;
    run += e3; eo.w = e3; io.w = 1.f / run;
    ((float4*)(g_e      + b * T_DIM))[tid] = eo;
    ((float4*)(g_invden + b * T_DIM))[tid] = io;
}

// ---------------------------------------------------------------------------
// Phase A: per-(batch, chunk) partial sums of e*y over the chunk, per d.
//          y = P[:, D:2D]
// ---------------------------------------------------------------------------
__global__ void __launch_bounds__(256) partial_kernel()
{
    const int c = blockIdx.x, b = blockIdx.y;
    const int t0 = c * CSIZE;
    __shared__ float se[CSIZE];
    if (threadIdx.x < CSIZE) se[threadIdx.x] = g_e[b * T_DIM + t0 + threadIdx.x];
    __syncthreads();

    float acc[4] = {0.f, 0.f, 0.f, 0.f};
    const float* base = g_P + ((size_t)(b * T_DIM + t0)) * N_P + D_DIM;
    for (int tt = 0; tt < CSIZE; tt++) {
        const float ee = se[tt];
        const float* row = base + (size_t)tt * N_P;
        #pragma unroll
        for (int i = 0; i < 4; i++)
            acc[i] = fmaf(ee, row[threadIdx.x + i * 256], acc[i]);
    }
    float* pp = g_part + ((size_t)(b * NCHUNK + c)) * D_DIM;
    #pragma unroll
    for (int i = 0; i < 4; i++) pp[threadIdx.x + i * 256] = acc[i];
}

// ---------------------------------------------------------------------------
// Phase B: convert partials to exclusive prefix over chunks for each (b,d).
// ---------------------------------------------------------------------------
__global__ void __launch_bounds__(256) chunk_scan_kernel()
{
    const int idx = blockIdx.x * 256 + threadIdx.x;   // 8192 threads
    const int b = idx >> 10, d = idx & (D_DIM - 1);
    float run = 0.f;
    #pragma unroll
    for (int c = 0; c < NCHUNK; c++) {
        const size_t off = ((size_t)(b * NCHUNK + c)) * D_DIM + d;
        const float v = g_part[off];
        g_part[off] = run;
        run += v;
    }
}

// ---------------------------------------------------------------------------
// Phase C: out[m,d] = tanh(cumsum(e*y)*invden + z + bc[d]),
//          z = P[:, 2D:3D]
// ---------------------------------------------------------------------------
__global__ void __launch_bounds__(1024) final_kernel(
    const float* __restrict__ bc, float* __restrict__ out)
{
    const int c = blockIdx.x, b = blockIdx.y;
    const int d = threadIdx.x;
    const int t0 = c * CSIZE;
    __shared__ float se[CSIZE], si[CSIZE];
    if (d < CSIZE)                se[d]          = g_e[b * T_DIM + t0 + d];
    else if (d < 2 * CSIZE)       si[d - CSIZE]  = g_invden[b * T_DIM + t0 + d - CSIZE];
    __syncthreads();

    float acc = g_part[((size_t)(b * NCHUNK + c)) * D_DIM + d];
    const float bias = bc[d];
    const size_t mbase = (size_t)(b * T_DIM + t0);
    for (int tt = 0; tt < CSIZE; tt++) {
        const size_t m = mbase + tt;
        const float y = g_P[m * N_P + D_DIM + d];
        const float z = g_P[m * N_P + 2 * D_DIM + d];
        acc = fmaf(se[tt], y, acc);
        out[m * (size_t)D_DIM + d] = tanhf(fmaf(acc, si[tt], z + bias));
    }
}

// ---------------------------------------------------------------------------
extern "C" void kernel_launch(void* const* d_in, const int* in_sizes, int n_in,
                              void* d_out, int out_size)
{
    const float* x  = (const float*)d_in[0];   // [8,4096,1024]
    const float* W1 = (const float*)d_in[1];   // [1024,1024] (e,d)
    const float* b1 = (const float*)d_in[2];   // [1024]
    const float* w2 = (const float*)d_in[3];   // [1,1024]
    const float* b2 = (const float*)d_in[4];   // [1]
    const float* Wc = (const float*)d_in[5];   // [1024,2048] (dout,k)
    const float* bc = (const float*)d_in[6];   // [1024]
    float* out = (float*)d_out;

    float* P = nullptr;
    cudaGetSymbolAddress((void**)&P, g_P);

    const dim3 gemm_grid(D_DIM / 128, M_TOK / 128);   // (8, 256)
    // P[:, 0:D]    = x @ W1^T + b1
    sgemm_nt<<<gemm_grid, 256>>>(x, D_DIM, W1, D_DIM, b1, P, N_P, D_DIM);
    // P[:, D:2D]   = x @ WcL^T   (Wc[:, 0:D])
    sgemm_nt<<<gemm_grid, 256>>>(x, D_DIM, Wc, 2 * D_DIM, nullptr, P + D_DIM, N_P, D_DIM);
    // P[:, 2D:3D]  = x @ WcR^T   (Wc[:, D:2D])
    sgemm_nt<<<gemm_grid, 256>>>(x, D_DIM, Wc + D_DIM, 2 * D_DIM, nullptr, P + 2 * D_DIM, N_P, D_DIM);

    score_kernel<<<M_TOK, 256>>>(w2, b2);
    softmax_scan_kernel<<<B_DIM, 1024>>>();
    partial_kernel<<<dim3(NCHUNK, B_DIM), 256>>>();
    chunk_scan_kernel<<<(B_DIM * D_DIM) / 256, 256>>>();
    final_kernel<<<dim3(NCHUNK, B_DIM), 1024>>>(bc, out);
}